// round 1
// baseline (speedup 1.0000x reference)
#include <cuda_runtime.h>

#define NN   50000
#define EE   800000
#define DIN  500
#define HID  100
#define DOUT 64
#define LN_EPS 1e-5f

// ---------------- scratch (static device globals: allowed) ----------------
__device__ float g_buf1[NN * HID];
__device__ float g_buf2[NN * HID];
__device__ float g_buf3[NN * HID];
__device__ float g_buf4[NN * HID];
__device__ int   g_cnt[NN];
__device__ int   g_rowptr[NN + 1];
__device__ int   g_cur[NN];
__device__ int   g_csr[EE];
__device__ float g_dinv[NN];

// ---------------- f32x2 helpers (Blackwell packed FMA) ----------------
__device__ __forceinline__ unsigned long long ffma2(unsigned long long a,
                                                    unsigned long long b,
                                                    unsigned long long c) {
    unsigned long long d;
    asm("fma.rn.f32x2 %0, %1, %2, %3;" : "=l"(d) : "l"(a), "l"(b), "l"(c));
    return d;
}
__device__ __forceinline__ unsigned long long pack2(float lo, float hi) {
    unsigned long long d;
    asm("mov.b64 %0, {%1, %2};" : "=l"(d) : "f"(lo), "f"(hi));
    return d;
}
__device__ __forceinline__ float2 unpack2(unsigned long long v) {
    float2 r;
    asm("mov.b64 {%0, %1}, %2;" : "=f"(r.x), "=f"(r.y) : "l"(v));
    return r;
}

// ---------------- GEMM: out[M,NOUT] = A[M,K] @ W[K,NOUT] (+bias) (*dinv[row]) ----
// Block: NOUT*8 threads, 64 rows. Thread (col, rs) owns col for 4 row-pairs.
// SMEM A-tile is pair-interleaved so an LDS.128 yields two packed f32x2 operands.
template <int K, int NOUT>
__global__ void __launch_bounds__(NOUT * 8) gemm_kernel(
    const float* __restrict__ A, const float* __restrict__ W,
    const float* __restrict__ bias, const float* __restrict__ dinv,
    float* __restrict__ out, int M)
{
    constexpr int KT = 100;
    constexpr int ROWS = 64;
    __shared__ __align__(16) float sA[ROWS * KT];

    const int tid  = threadIdx.x;
    const int col  = tid % NOUT;
    const int rs   = tid / NOUT;            // 0..7
    const int row0 = blockIdx.x * ROWS;

    unsigned long long acc0 = 0ull, acc1 = 0ull, acc2 = 0ull, acc3 = 0ull;

    for (int k0 = 0; k0 < K; k0 += KT) {
        // stage A[row0:row0+64, k0:k0+KT] into pair-interleaved layout
        for (int idx = tid; idx < ROWS * KT; idx += NOUT * 8) {
            int r = idx / KT, k = idx % KT;
            int grow = row0 + r;
            float v = (grow < M) ? A[(long long)grow * K + (k0 + k)] : 0.0f;
            int p = r >> 1, rp = r & 1, k2 = k >> 1, kp = k & 1;
            sA[(p * (KT / 2) + k2) * 4 + kp * 2 + rp] = v;
        }
        __syncthreads();

        const float* wp = W + k0 * NOUT + col;
        const ulonglong2* a0 = ((const ulonglong2*)sA) + (rs     ) * (KT / 2);
        const ulonglong2* a1 = ((const ulonglong2*)sA) + (rs +  8) * (KT / 2);
        const ulonglong2* a2 = ((const ulonglong2*)sA) + (rs + 16) * (KT / 2);
        const ulonglong2* a3 = ((const ulonglong2*)sA) + (rs + 24) * (KT / 2);

        #pragma unroll 5
        for (int k2 = 0; k2 < KT / 2; k2++) {
            float w0 = __ldg(wp);
            float w1 = __ldg(wp + NOUT);
            wp += 2 * NOUT;
            unsigned long long pw0 = pack2(w0, w0);
            unsigned long long pw1 = pack2(w1, w1);
            ulonglong2 va;
            va = a0[k2]; acc0 = ffma2(va.x, pw0, acc0); acc0 = ffma2(va.y, pw1, acc0);
            va = a1[k2]; acc1 = ffma2(va.x, pw0, acc1); acc1 = ffma2(va.y, pw1, acc1);
            va = a2[k2]; acc2 = ffma2(va.x, pw0, acc2); acc2 = ffma2(va.y, pw1, acc2);
            va = a3[k2]; acc3 = ffma2(va.x, pw0, acc3); acc3 = ffma2(va.y, pw1, acc3);
        }
        __syncthreads();
    }

    float b = bias ? bias[col] : 0.0f;
    unsigned long long accs[4] = {acc0, acc1, acc2, acc3};
    #pragma unroll
    for (int j = 0; j < 4; j++) {
        int p  = rs + 8 * j;
        int r0 = row0 + 2 * p;
        int r1 = r0 + 1;
        float2 v = unpack2(accs[j]);
        if (r0 < M) {
            float s = dinv ? dinv[r0] : 1.0f;
            out[(long long)r0 * NOUT + col] = (v.x + b) * s;
        }
        if (r1 < M) {
            float s = dinv ? dinv[r1] : 1.0f;
            out[(long long)r1 * NOUT + col] = (v.y + b) * s;
        }
    }
}

// ---------------- LayerNorm + ReLU, in place, warp per row (HID=100) ----------
__global__ void ln_relu_kernel(float* __restrict__ x, const float* __restrict__ g,
                               const float* __restrict__ be)
{
    int warp = (blockIdx.x * blockDim.x + threadIdx.x) >> 5;
    int lane = threadIdx.x & 31;
    if (warp >= NN) return;
    float* row = x + (long long)warp * HID;
    float v0 = row[lane];
    float v1 = row[lane + 32];
    float v2 = row[lane + 64];
    float v3 = (lane < 4) ? row[lane + 96] : 0.0f;
    float s  = v0 + v1 + v2 + v3;
    float sq = v0 * v0 + v1 * v1 + v2 * v2 + v3 * v3;
    #pragma unroll
    for (int o = 16; o; o >>= 1) {
        s  += __shfl_xor_sync(0xffffffffu, s, o);
        sq += __shfl_xor_sync(0xffffffffu, sq, o);
    }
    float mu   = s * (1.0f / HID);
    float var  = sq * (1.0f / HID) - mu * mu;
    float rstd = rsqrtf(var + LN_EPS);
    row[lane]      = fmaxf(0.0f, (v0 - mu) * rstd * g[lane]      + be[lane]);
    row[lane + 32] = fmaxf(0.0f, (v1 - mu) * rstd * g[lane + 32] + be[lane + 32]);
    row[lane + 64] = fmaxf(0.0f, (v2 - mu) * rstd * g[lane + 64] + be[lane + 64]);
    if (lane < 4)
        row[lane + 96] = fmaxf(0.0f, (v3 - mu) * rstd * g[lane + 96] + be[lane + 96]);
}

// ---------------- CSR construction ----------------
__global__ void zero_cnt_kernel() {
    int i = blockIdx.x * blockDim.x + threadIdx.x;
    if (i < NN) g_cnt[i] = 0;
}
__global__ void count_kernel(const int* __restrict__ tgt) {
    int e = blockIdx.x * blockDim.x + threadIdx.x;
    if (e < EE) atomicAdd(&g_cnt[tgt[e]], 1);
}
__global__ void scan_kernel() {
    __shared__ int s[1024];
    int tid = threadIdx.x;
    int offset = 0;
    for (int base = 0; base < NN; base += 1024) {
        int i = base + tid;
        int v = (i < NN) ? g_cnt[i] : 0;
        s[tid] = v;
        __syncthreads();
        #pragma unroll
        for (int d = 1; d < 1024; d <<= 1) {
            int t = (tid >= d) ? s[tid - d] : 0;
            __syncthreads();
            s[tid] += t;
            __syncthreads();
        }
        int incl = s[tid];
        if (i < NN) {
            int ex = offset + incl - v;
            g_rowptr[i] = ex;
            g_cur[i]    = ex;
        }
        int tot = s[1023];
        __syncthreads();
        offset += tot;
    }
    if (tid == 0) g_rowptr[NN] = offset;
}
__global__ void fill_kernel(const int* __restrict__ src, const int* __restrict__ tgt) {
    int e = blockIdx.x * blockDim.x + threadIdx.x;
    if (e < EE) {
        int pos = atomicAdd(&g_cur[tgt[e]], 1);
        g_csr[pos] = src[e];
    }
}
__global__ void dinv_kernel() {
    int i = blockIdx.x * blockDim.x + threadIdx.x;
    if (i < NN) g_dinv[i] = rsqrtf((float)(g_cnt[i] + 1));
}

// ---------------- gather: out[v] = epi(init[v] + sum_{e: tgt=v} msg[src_e]) -----
// MODE 0: relu                       (RGCN)
// MODE 1: *dinv[v] + bias, relu      (GCNConv 1; msg already scaled by dinv[src])
// MODE 2: *dinv[v] + bias, log_softmax over C (final GCNConv)
template <int C, int MODE>
__global__ void gather_kernel(const float* __restrict__ msg,
                              const float* __restrict__ init,
                              const float* __restrict__ bias,
                              float* __restrict__ out)
{
    int warp = (blockIdx.x * blockDim.x + threadIdx.x) >> 5;
    int lane = threadIdx.x & 31;
    if (warp >= NN) return;
    constexpr int C4 = C / 4;
    bool act = lane < C4;

    float4 acc = make_float4(0.f, 0.f, 0.f, 0.f);
    if (act) acc = __ldg((const float4*)(init + (long long)warp * C) + lane);

    int beg = g_rowptr[warp];
    int end = g_rowptr[warp + 1];
    int e = beg;
    for (; e + 1 < end; e += 2) {
        int s0 = g_csr[e];
        int s1 = g_csr[e + 1];
        if (act) {
            float4 t0 = __ldg((const float4*)(msg + (long long)s0 * C) + lane);
            float4 t1 = __ldg((const float4*)(msg + (long long)s1 * C) + lane);
            acc.x += t0.x + t1.x; acc.y += t0.y + t1.y;
            acc.z += t0.z + t1.z; acc.w += t0.w + t1.w;
        }
    }
    if (e < end) {
        int s0 = g_csr[e];
        if (act) {
            float4 t0 = __ldg((const float4*)(msg + (long long)s0 * C) + lane);
            acc.x += t0.x; acc.y += t0.y; acc.z += t0.z; acc.w += t0.w;
        }
    }

    if (MODE == 0) {
        if (act) {
            float4 r = make_float4(fmaxf(0.f, acc.x), fmaxf(0.f, acc.y),
                                   fmaxf(0.f, acc.z), fmaxf(0.f, acc.w));
            *((float4*)(out + (long long)warp * C) + lane) = r;
        }
    } else {
        float d = g_dinv[warp];
        float4 t = make_float4(0.f, 0.f, 0.f, 0.f);
        if (act) {
            float4 b4 = __ldg((const float4*)bias + lane);
            t.x = acc.x * d + b4.x;
            t.y = acc.y * d + b4.y;
            t.z = acc.z * d + b4.z;
            t.w = acc.w * d + b4.w;
        }
        if (MODE == 1) {
            if (act) {
                float4 r = make_float4(fmaxf(0.f, t.x), fmaxf(0.f, t.y),
                                       fmaxf(0.f, t.z), fmaxf(0.f, t.w));
                *((float4*)(out + (long long)warp * C) + lane) = r;
            }
        } else {
            // log_softmax across the C values held by lanes [0, C4)
            float m = act ? fmaxf(fmaxf(t.x, t.y), fmaxf(t.z, t.w)) : -1e30f;
            #pragma unroll
            for (int o = 16; o; o >>= 1) m = fmaxf(m, __shfl_xor_sync(0xffffffffu, m, o));
            float se = act ? (expf(t.x - m) + expf(t.y - m) + expf(t.z - m) + expf(t.w - m))
                           : 0.0f;
            #pragma unroll
            for (int o = 16; o; o >>= 1) se += __shfl_xor_sync(0xffffffffu, se, o);
            float lse = logf(se);
            if (act) {
                float4 r = make_float4(t.x - m - lse, t.y - m - lse,
                                       t.z - m - lse, t.w - m - lse);
                *((float4*)(out + (long long)warp * C) + lane) = r;
            }
        }
    }
}

// ---------------- launcher ----------------
extern "C" void kernel_launch(void* const* d_in, const int* in_sizes, int n_in,
                              void* d_out, int out_size)
{
    const float* X     = (const float*)d_in[0];
    const int*   EI    = (const int*)d_in[1];
    // d_in[2] = edge_attr (single relation) — unused
    const float* W1    = (const float*)d_in[3];
    const float* b1    = (const float*)d_in[4];
    const float* g1    = (const float*)d_in[5];
    const float* be1   = (const float*)d_in[6];
    const float* W2    = (const float*)d_in[7];
    const float* b2    = (const float*)d_in[8];
    const float* g2    = (const float*)d_in[9];
    const float* be2   = (const float*)d_in[10];
    const float* Wrel  = (const float*)d_in[11];
    const float* Wself = (const float*)d_in[12];
    const float* rb    = (const float*)d_in[13];
    const float* c1W   = (const float*)d_in[14];
    const float* c1b   = (const float*)d_in[15];
    const float* c2W   = (const float*)d_in[16];
    const float* c2b   = (const float*)d_in[17];

    const int* src = EI;
    const int* tgt = EI + EE;

    float *buf1, *buf2, *buf3, *buf4, *dinvp;
    cudaGetSymbolAddress((void**)&buf1, g_buf1);
    cudaGetSymbolAddress((void**)&buf2, g_buf2);
    cudaGetSymbolAddress((void**)&buf3, g_buf3);
    cudaGetSymbolAddress((void**)&buf4, g_buf4);
    cudaGetSymbolAddress((void**)&dinvp, g_dinv);

    // --- CSR + degrees (cheap; also reused by all 3 scatter stages) ---
    zero_cnt_kernel<<<(NN + 255) / 256, 256>>>();
    count_kernel<<<(EE + 255) / 256, 256>>>(tgt);
    scan_kernel<<<1, 1024>>>();
    fill_kernel<<<(EE + 255) / 256, 256>>>(src, tgt);
    dinv_kernel<<<(NN + 255) / 256, 256>>>();

    const int GB = (NN + 63) / 64;       // gemm blocks
    const int WB = (NN + 7) / 8;         // warp-per-row blocks (256 thr)

    // --- transform MLP ---
    gemm_kernel<DIN, HID><<<GB, HID * 8>>>(X, W1, b1, nullptr, buf1, NN);
    ln_relu_kernel<<<WB, 256>>>(buf1, g1, be1);
    gemm_kernel<HID, HID><<<GB, HID * 8>>>(buf1, W2, b2, nullptr, buf2, NN);
    ln_relu_kernel<<<WB, 256>>>(buf2, g2, be2);

    // --- RGCN layer: buf3 = x@Wrel (messages), buf4 = x@Wself + rb (init) ---
    gemm_kernel<HID, HID><<<GB, HID * 8>>>(buf2, Wrel, nullptr, nullptr, buf3, NN);
    gemm_kernel<HID, HID><<<GB, HID * 8>>>(buf2, Wself, rb, nullptr, buf4, NN);
    gather_kernel<HID, 0><<<WB, 256>>>(buf3, buf4, nullptr, buf2);  // relu epi

    // --- GCNConv 1: hs = (x@c1W)*dinv ; out = relu(dinv*(hs[v]+sum hs[src]) + b)
    gemm_kernel<HID, HID><<<GB, HID * 8>>>(buf2, c1W, nullptr, dinvp, buf1, NN);
    gather_kernel<HID, 1><<<WB, 256>>>(buf1, buf1, c1b, buf3);

    // --- GCNConv 2 (100->64) + log_softmax ---
    gemm_kernel<HID, DOUT><<<GB, DOUT * 8>>>(buf3, c2W, nullptr, dinvp, buf4, NN);
    gather_kernel<DOUT, 2><<<WB, 256>>>(buf4, buf4, c2b, (float*)d_out);
}

// round 4
// speedup vs baseline: 1.7284x; 1.7284x over previous
#include <cuda_runtime.h>
#include <cuda_bf16.h>
#include <cstdint>

#define NN   50000
#define EE   800000
#define DIN  500
#define HID  100
#define DOUT 64
#define LN_EPS 1e-5f

// ---------------- scratch (static device globals: allowed) ----------------
__device__ float g_buf1[NN * HID];
__device__ float g_buf2[NN * HID];
__device__ float g_buf3[NN * HID];
__device__ float g_buf4[NN * HID];
__device__ int   g_cnt[NN];
__device__ int   g_rowptr[NN + 1];
__device__ int   g_cur[NN];
__device__ int   g_csr[EE];
__device__ float g_dinv[NN];
// pre-packed per-lane B fragments (hi/lo bf16 pairs), uint4 per (kstep,ntile,lane)
__device__ uint4 g_wfrag[26752];

// wfrag offsets (uint4 elements): layout [kstep][ntile][lane]
#define OFF_W1   0       // 32 ksteps * 13 nt * 32 = 13312
#define OFF_W2   13312   // 7 * 13 * 32 = 2912
#define OFF_REL  16224
#define OFF_SELF 19136
#define OFF_C1   22048
#define OFF_C2   24960   // 7 * 8 * 32 = 1792

// ---------------- helpers ----------------
__device__ __forceinline__ uint32_t smem_u32(const void* p) {
    uint32_t a;
    asm("{ .reg .u64 t; cvta.to.shared.u64 t, %1; cvt.u32.u64 %0, t; }"
        : "=r"(a) : "l"(p));
    return a;
}
__device__ __forceinline__ uint32_t sw128(uint32_t off) {
    return off ^ ((off >> 3) & 0x70);
}
__device__ __forceinline__ uint32_t pack_bf(float a, float b) {
    __nv_bfloat16 ha = __float2bfloat16(a), hb = __float2bfloat16(b);
    return (uint32_t)__bfloat16_as_ushort(ha) |
           ((uint32_t)__bfloat16_as_ushort(hb) << 16);
}
__device__ __forceinline__ void split_pair(float a, float b, uint32_t& h, uint32_t& l) {
    __nv_bfloat16 ha = __float2bfloat16(a), hb = __float2bfloat16(b);
    float ra = a - __bfloat162float(ha);
    float rb = b - __bfloat162float(hb);
    h = pack_bf(a, b);           // pack_bf rounds to bf16 internally
    l = pack_bf(ra, rb);
}
__device__ __forceinline__ void ldm_x4(uint32_t& r0, uint32_t& r1, uint32_t& r2,
                                       uint32_t& r3, uint32_t addr) {
    asm volatile("ldmatrix.sync.aligned.m8n8.x4.shared.b16 {%0,%1,%2,%3}, [%4];"
                 : "=r"(r0), "=r"(r1), "=r"(r2), "=r"(r3) : "r"(addr));
}
__device__ __forceinline__ void mma_bf16(float* d, uint32_t a0, uint32_t a1,
                                         uint32_t a2, uint32_t a3,
                                         uint32_t b0, uint32_t b1) {
    asm volatile(
        "mma.sync.aligned.m16n8k16.row.col.f32.bf16.bf16.f32 "
        "{%0,%1,%2,%3}, {%4,%5,%6,%7}, {%8,%9}, {%0,%1,%2,%3};"
        : "+f"(d[0]), "+f"(d[1]), "+f"(d[2]), "+f"(d[3])
        : "r"(a0), "r"(a1), "r"(a2), "r"(a3), "r"(b0), "r"(b1));
}

// ---------------- B-fragment pre-pack ----------------
// W[K,NOUT] fp32 -> per-lane mma fragments, uint4 {bh0, bh1, bl0, bl1}
// lane mapping (m16n8k16 row.col B): n = nt*8 + lane/4, k0 = ks*16 + (lane%4)*2
__global__ void wfrag_kernel(const float* __restrict__ W, int K, int NOUT,
                             int KSTEPS, int NT8, uint4* __restrict__ out)
{
    int idx = blockIdx.x * blockDim.x + threadIdx.x;
    if (idx >= KSTEPS * NT8 * 32) return;
    int lane = idx & 31;
    int nt   = (idx >> 5) % NT8;
    int ks   = idx / (32 * NT8);
    int n    = nt * 8 + (lane >> 2);
    int k0   = ks * 16 + (lane & 3) * 2;

    float w[4];
    int kk[4] = {k0, k0 + 1, k0 + 8, k0 + 9};
    #pragma unroll
    for (int i = 0; i < 4; i++)
        w[i] = (kk[i] < K && n < NOUT) ? W[(size_t)kk[i] * NOUT + n] : 0.0f;

    float hi[4], lo[4];
    #pragma unroll
    for (int i = 0; i < 4; i++) {
        hi[i] = __bfloat162float(__float2bfloat16(w[i]));
        lo[i] = w[i] - hi[i];
    }
    out[idx] = make_uint4(pack_bf(hi[0], hi[1]), pack_bf(hi[2], hi[3]),
                          pack_bf(lo[0], lo[1]), pack_bf(lo[2], lo[3]));
}

// ---------------- mma.sync GEMM with fused epilogue ----------------
// out[M, NOUT] = epi( A[M,K] @ W[K,NOUT] ), 3-term bf16 split, fp32 accum.
// EPI: 0 = +bias(optional)  1 = +bias, LayerNorm, ReLU  2 = *dinv[row]
template <int K, int KSTEPS, int NT8, int NOUT, int EPI>
__global__ void __launch_bounds__(256) gemm_mma(
    const float* __restrict__ A, const uint4* __restrict__ WF,
    const float* __restrict__ bias, const float* __restrict__ gamma,
    const float* __restrict__ beta, const float* __restrict__ dinv,
    float* __restrict__ out, int M)
{
    extern __shared__ char rawsm[];
    char* smem = (char*)(((uintptr_t)rawsm + 1023) & ~(uintptr_t)1023);
    const uint32_t abase = smem_u32(smem);
    constexpr int SM_AL = 16384;
    constexpr int NCHUNK = (KSTEPS + 3) / 4;

    const int tid = threadIdx.x, wid = tid >> 5, lane = tid & 31;
    const int row0 = blockIdx.x * 128;

    float acc[NT8][4];
    #pragma unroll
    for (int nt = 0; nt < NT8; nt++)
        #pragma unroll
        for (int j = 0; j < 4; j++) acc[nt][j] = 0.0f;

    const uint32_t a_off0 =
        (uint32_t)((wid * 16 + (lane & 15)) * 128 + (lane >> 4) * 16);

    for (int c0 = 0; c0 < NCHUNK; c0++) {
        const int k0 = c0 * 64;
        // ---- stage A chunk: fp32 -> bf16 hi/lo, SW128 swizzled ----
        #pragma unroll
        for (int u0 = 0; u0 < 1024; u0 += 256) {
            int u = u0 + tid;
            int m = u >> 3, cc = u & 7;
            int grow = row0 + m;
            int k = k0 + cc * 8;
            float x0 = 0.f, x1 = 0.f, x2 = 0.f, x3 = 0.f;
            float x4 = 0.f, x5 = 0.f, x6 = 0.f, x7 = 0.f;
            if (grow < M) {
                const float* ap = A + (size_t)grow * K + k;
                if (k < K)     { float4 f = __ldg((const float4*)ap);
                                 x0 = f.x; x1 = f.y; x2 = f.z; x3 = f.w; }
                if (k + 4 < K) { float4 f = __ldg((const float4*)(ap + 4));
                                 x4 = f.x; x5 = f.y; x6 = f.z; x7 = f.w; }
            }
            uint4 h, l;
            split_pair(x0, x1, h.x, l.x);
            split_pair(x2, x3, h.y, l.y);
            split_pair(x4, x5, h.z, l.z);
            split_pair(x6, x7, h.w, l.w);
            uint32_t off = sw128((uint32_t)(m * 128 + cc * 16));
            *(uint4*)(smem + off)         = h;
            *(uint4*)(smem + SM_AL + off) = l;
        }
        __syncthreads();

        const int nks = (KSTEPS - c0 * 4 < 4) ? (KSTEPS - c0 * 4) : 4;
        for (int ks = 0; ks < nks; ks++) {
            uint32_t off = sw128(a_off0 + (uint32_t)(ks * 32));
            uint32_t ah0, ah1, ah2, ah3, al0, al1, al2, al3;
            ldm_x4(ah0, ah1, ah2, ah3, abase + off);
            ldm_x4(al0, al1, al2, al3, abase + SM_AL + off);
            const uint4* wp = WF + (size_t)(c0 * 4 + ks) * NT8 * 32 + lane;
            #pragma unroll
            for (int nt = 0; nt < NT8; nt++) {
                uint4 f = __ldg(wp + nt * 32);
                mma_bf16(acc[nt], ah0, ah1, ah2, ah3, f.x, f.y);
                mma_bf16(acc[nt], al0, al1, al2, al3, f.x, f.y);
                mma_bf16(acc[nt], ah0, ah1, ah2, ah3, f.z, f.w);
            }
        }
        __syncthreads();
    }

    // ---- epilogue ----
    // D mapping: d0,d1 -> row r0 = wid*16 + lane/4, cols n0,n0+1; d2,d3 -> r0+8
    const int r0 = row0 + wid * 16 + (lane >> 2);
    const int r1 = r0 + 8;
    const int cbase = (lane & 3) * 2;

    if constexpr (EPI == 1) {
        float s0 = 0.f, q0 = 0.f, s1 = 0.f, q1 = 0.f;
        #pragma unroll
        for (int nt = 0; nt < NT8; nt++) {
            int n0 = nt * 8 + cbase;
            float b0 = 0.f, b1 = 0.f;
            if (n0 < NOUT) { float2 bb = *(const float2*)(bias + n0); b0 = bb.x; b1 = bb.y; }
            float t;
            t = acc[nt][0] + b0; acc[nt][0] = t; s0 += t; q0 += t * t;
            t = acc[nt][1] + b1; acc[nt][1] = t; s0 += t; q0 += t * t;
            t = acc[nt][2] + b0; acc[nt][2] = t; s1 += t; q1 += t * t;
            t = acc[nt][3] + b1; acc[nt][3] = t; s1 += t; q1 += t * t;
        }
        #pragma unroll
        for (int o = 1; o <= 2; o <<= 1) {
            s0 += __shfl_xor_sync(0xffffffffu, s0, o);
            q0 += __shfl_xor_sync(0xffffffffu, q0, o);
            s1 += __shfl_xor_sync(0xffffffffu, s1, o);
            q1 += __shfl_xor_sync(0xffffffffu, q1, o);
        }
        float mu0 = s0 * (1.0f / NOUT), mu1 = s1 * (1.0f / NOUT);
        float rs0 = rsqrtf(q0 * (1.0f / NOUT) - mu0 * mu0 + LN_EPS);
        float rs1 = rsqrtf(q1 * (1.0f / NOUT) - mu1 * mu1 + LN_EPS);
        #pragma unroll
        for (int nt = 0; nt < NT8; nt++) {
            int n0 = nt * 8 + cbase;
            if (n0 < NOUT) {
                float2 gg = *(const float2*)(gamma + n0);
                float2 bb = *(const float2*)(beta + n0);
                acc[nt][0] = fmaxf(0.f, (acc[nt][0] - mu0) * rs0 * gg.x + bb.x);
                acc[nt][1] = fmaxf(0.f, (acc[nt][1] - mu0) * rs0 * gg.y + bb.y);
                acc[nt][2] = fmaxf(0.f, (acc[nt][2] - mu1) * rs1 * gg.x + bb.x);
                acc[nt][3] = fmaxf(0.f, (acc[nt][3] - mu1) * rs1 * gg.y + bb.y);
            }
        }
    } else if constexpr (EPI == 2) {
        float d0 = (r0 < M) ? dinv[r0] : 0.f;
        float d1 = (r1 < M) ? dinv[r1] : 0.f;
        #pragma unroll
        for (int nt = 0; nt < NT8; nt++) {
            acc[nt][0] *= d0; acc[nt][1] *= d0;
            acc[nt][2] *= d1; acc[nt][3] *= d1;
        }
    } else {
        if (bias) {
            #pragma unroll
            for (int nt = 0; nt < NT8; nt++) {
                int n0 = nt * 8 + cbase;
                if (n0 < NOUT) {
                    float2 bb = *(const float2*)(bias + n0);
                    acc[nt][0] += bb.x; acc[nt][1] += bb.y;
                    acc[nt][2] += bb.x; acc[nt][3] += bb.y;
                }
            }
        }
    }

    #pragma unroll
    for (int nt = 0; nt < NT8; nt++) {
        int n0 = nt * 8 + cbase;
        if (n0 < NOUT) {
            if (r0 < M)
                *(float2*)(out + (size_t)r0 * NOUT + n0) =
                    make_float2(acc[nt][0], acc[nt][1]);
            if (r1 < M)
                *(float2*)(out + (size_t)r1 * NOUT + n0) =
                    make_float2(acc[nt][2], acc[nt][3]);
        }
    }
}

// ---------------- CSR construction ----------------
__global__ void zero_cnt_kernel() {
    int i = blockIdx.x * blockDim.x + threadIdx.x;
    if (i < NN) g_cnt[i] = 0;
}
__global__ void count_kernel(const int* __restrict__ tgt) {
    int e = blockIdx.x * blockDim.x + threadIdx.x;
    if (e < EE) atomicAdd(&g_cnt[tgt[e]], 1);
}
__global__ void scan_kernel() {
    __shared__ int s[1024];
    int tid = threadIdx.x;
    int offset = 0;
    for (int base = 0; base < NN; base += 1024) {
        int i = base + tid;
        int v = (i < NN) ? g_cnt[i] : 0;
        s[tid] = v;
        __syncthreads();
        #pragma unroll
        for (int d = 1; d < 1024; d <<= 1) {
            int t = (tid >= d) ? s[tid - d] : 0;
            __syncthreads();
            s[tid] += t;
            __syncthreads();
        }
        int incl = s[tid];
        if (i < NN) {
            int ex = offset + incl - v;
            g_rowptr[i] = ex;
            g_cur[i]    = ex;
        }
        int tot = s[1023];
        __syncthreads();
        offset += tot;
    }
    if (tid == 0) g_rowptr[NN] = offset;
}
__global__ void fill_kernel(const int* __restrict__ src, const int* __restrict__ tgt) {
    int e = blockIdx.x * blockDim.x + threadIdx.x;
    if (e < EE) {
        int pos = atomicAdd(&g_cur[tgt[e]], 1);
        g_csr[pos] = src[e];
    }
}
__global__ void dinv_kernel() {
    int i = blockIdx.x * blockDim.x + threadIdx.x;
    if (i < NN) g_dinv[i] = rsqrtf((float)(g_cnt[i] + 1));
}

// ---------------- gather: out[v] = epi(init[v] + sum_{e: tgt=v} msg[src_e]) -----
template <int C, int MODE>
__global__ void gather_kernel(const float* __restrict__ msg,
                              const float* __restrict__ init,
                              const float* __restrict__ bias,
                              float* __restrict__ out)
{
    int warp = (blockIdx.x * blockDim.x + threadIdx.x) >> 5;
    int lane = threadIdx.x & 31;
    if (warp >= NN) return;
    constexpr int C4 = C / 4;
    bool act = lane < C4;

    float4 acc = make_float4(0.f, 0.f, 0.f, 0.f);
    if (act) acc = __ldg((const float4*)(init + (long long)warp * C) + lane);

    int beg = g_rowptr[warp];
    int end = g_rowptr[warp + 1];
    int e = beg;
    for (; e + 1 < end; e += 2) {
        int s0 = g_csr[e];
        int s1 = g_csr[e + 1];
        if (act) {
            float4 t0 = __ldg((const float4*)(msg + (long long)s0 * C) + lane);
            float4 t1 = __ldg((const float4*)(msg + (long long)s1 * C) + lane);
            acc.x += t0.x + t1.x; acc.y += t0.y + t1.y;
            acc.z += t0.z + t1.z; acc.w += t0.w + t1.w;
        }
    }
    if (e < end) {
        int s0 = g_csr[e];
        if (act) {
            float4 t0 = __ldg((const float4*)(msg + (long long)s0 * C) + lane);
            acc.x += t0.x; acc.y += t0.y; acc.z += t0.z; acc.w += t0.w;
        }
    }

    if (MODE == 0) {
        if (act) {
            float4 r = make_float4(fmaxf(0.f, acc.x), fmaxf(0.f, acc.y),
                                   fmaxf(0.f, acc.z), fmaxf(0.f, acc.w));
            *((float4*)(out + (long long)warp * C) + lane) = r;
        }
    } else {
        float d = g_dinv[warp];
        float4 t = make_float4(0.f, 0.f, 0.f, 0.f);
        if (act) {
            float4 b4 = __ldg((const float4*)bias + lane);
            t.x = acc.x * d + b4.x;
            t.y = acc.y * d + b4.y;
            t.z = acc.z * d + b4.z;
            t.w = acc.w * d + b4.w;
        }
        if (MODE == 1) {
            if (act) {
                float4 r = make_float4(fmaxf(0.f, t.x), fmaxf(0.f, t.y),
                                       fmaxf(0.f, t.z), fmaxf(0.f, t.w));
                *((float4*)(out + (long long)warp * C) + lane) = r;
            }
        } else {
            float m = act ? fmaxf(fmaxf(t.x, t.y), fmaxf(t.z, t.w)) : -1e30f;
            #pragma unroll
            for (int o = 16; o; o >>= 1) m = fmaxf(m, __shfl_xor_sync(0xffffffffu, m, o));
            float se = act ? (expf(t.x - m) + expf(t.y - m) + expf(t.z - m) + expf(t.w - m))
                           : 0.0f;
            #pragma unroll
            for (int o = 16; o; o >>= 1) se += __shfl_xor_sync(0xffffffffu, se, o);
            float lse = logf(se);
            if (act) {
                float4 r = make_float4(t.x - m - lse, t.y - m - lse,
                                       t.z - m - lse, t.w - m - lse);
                *((float4*)(out + (long long)warp * C) + lane) = r;
            }
        }
    }
}

// ---------------- launcher ----------------
extern "C" void kernel_launch(void* const* d_in, const int* in_sizes, int n_in,
                              void* d_out, int out_size)
{
    const float* X     = (const float*)d_in[0];
    const int*   EI    = (const int*)d_in[1];
    const float* W1    = (const float*)d_in[3];
    const float* b1    = (const float*)d_in[4];
    const float* g1    = (const float*)d_in[5];
    const float* be1   = (const float*)d_in[6];
    const float* W2    = (const float*)d_in[7];
    const float* b2    = (const float*)d_in[8];
    const float* g2    = (const float*)d_in[9];
    const float* be2   = (const float*)d_in[10];
    const float* Wrel  = (const float*)d_in[11];
    const float* Wself = (const float*)d_in[12];
    const float* rb    = (const float*)d_in[13];
    const float* c1W   = (const float*)d_in[14];
    const float* c1b   = (const float*)d_in[15];
    const float* c2W   = (const float*)d_in[16];
    const float* c2b   = (const float*)d_in[17];

    const int* src = EI;
    const int* tgt = EI + EE;

    float *buf1, *buf2, *buf3, *buf4, *dinvp;
    uint4* wf;
    cudaGetSymbolAddress((void**)&buf1, g_buf1);
    cudaGetSymbolAddress((void**)&buf2, g_buf2);
    cudaGetSymbolAddress((void**)&buf3, g_buf3);
    cudaGetSymbolAddress((void**)&buf4, g_buf4);
    cudaGetSymbolAddress((void**)&dinvp, g_dinv);
    cudaGetSymbolAddress((void**)&wf, g_wfrag);

    // --- B-fragment pre-pack (tiny) ---
    wfrag_kernel<<<(13312 + 255) / 256, 256>>>(W1,    DIN, HID, 32, 13, wf + OFF_W1);
    wfrag_kernel<<<(2912  + 255) / 256, 256>>>(W2,    HID, HID, 7,  13, wf + OFF_W2);
    wfrag_kernel<<<(2912  + 255) / 256, 256>>>(Wrel,  HID, HID, 7,  13, wf + OFF_REL);
    wfrag_kernel<<<(2912  + 255) / 256, 256>>>(Wself, HID, HID, 7,  13, wf + OFF_SELF);
    wfrag_kernel<<<(2912  + 255) / 256, 256>>>(c1W,   HID, HID, 7,  13, wf + OFF_C1);
    wfrag_kernel<<<(1792  + 255) / 256, 256>>>(c2W,   HID, DOUT, 7, 8,  wf + OFF_C2);

    // --- CSR + degrees ---
    zero_cnt_kernel<<<(NN + 255) / 256, 256>>>();
    count_kernel<<<(EE + 255) / 256, 256>>>(tgt);
    scan_kernel<<<1, 1024>>>();
    fill_kernel<<<(EE + 255) / 256, 256>>>(src, tgt);
    dinv_kernel<<<(NN + 255) / 256, 256>>>();

    const int MB = (NN + 127) / 128;   // 391
    const int WB = (NN + 7) / 8;       // gather blocks (256 thr, warp/node)
    const int SMEM = 2 * 16384 + 1024; // 33792

    // --- transform MLP (LN+ReLU fused) ---
    gemm_mma<DIN, 32, 13, HID, 1><<<MB, 256, SMEM>>>(
        X, wf + OFF_W1, b1, g1, be1, nullptr, buf1, NN);
    gemm_mma<HID, 7, 13, HID, 1><<<MB, 256, SMEM>>>(
        buf1, wf + OFF_W2, b2, g2, be2, nullptr, buf2, NN);

    // --- RGCN: buf3 = x@Wrel (messages), buf4 = x@Wself + rb ---
    gemm_mma<HID, 7, 13, HID, 0><<<MB, 256, SMEM>>>(
        buf2, wf + OFF_REL, nullptr, nullptr, nullptr, nullptr, buf3, NN);
    gemm_mma<HID, 7, 13, HID, 0><<<MB, 256, SMEM>>>(
        buf2, wf + OFF_SELF, rb, nullptr, nullptr, nullptr, buf4, NN);
    gather_kernel<HID, 0><<<WB, 256>>>(buf3, buf4, nullptr, buf2);

    // --- GCNConv 1 ---
    gemm_mma<HID, 7, 13, HID, 2><<<MB, 256, SMEM>>>(
        buf2, wf + OFF_C1, nullptr, nullptr, nullptr, dinvp, buf1, NN);
    gather_kernel<HID, 1><<<WB, 256>>>(buf1, buf1, c1b, buf3);

    // --- GCNConv 2 (100->64) + log_softmax ---
    gemm_mma<HID, 7, 8, DOUT, 2><<<MB, 256, SMEM>>>(
        buf3, wf + OFF_C2, nullptr, nullptr, nullptr, dinvp, buf4, NN);
    gather_kernel<DOUT, 2><<<WB, 256>>>(buf4, buf4, c2b, (float*)d_out);
}

// round 8
// speedup vs baseline: 2.0717x; 1.1986x over previous
#include <cuda_runtime.h>
#include <cuda_bf16.h>
#include <cuda_fp16.h>
#include <cstdint>

#define NN   50000
#define EE   800000
#define DIN  500
#define HID  100
#define DOUT 64
#define LN_EPS 1e-5f

// ---------------- scratch (static device globals: allowed) ----------------
__device__ float g_buf1[NN * HID];
__device__ float g_buf3[NN * HID];
__device__ float g_buf4[NN * HID];
__device__ int   g_cnt[NN];
__device__ int   g_rowptr[NN + 1];
__device__ int   g_cur[NN];
__device__ int   g_csr[EE];
__device__ float g_dinv[NN];
// split activation planes: [H plane NN*128][L plane NN*128] bf16
__device__ __nv_bfloat16 g_sp1[NN * 256];
__device__ __nv_bfloat16 g_sp2[NN * 256];
// pre-packed per-lane B fragments
__device__ uint4 g_wfrag[26752];

// wfrag offsets (uint4): W1(fp16) 32*13*32=13312 | W2 7*13*32=2912 |
// FUSED(rel+self) 7*26*32=5824 | C1 2912 | C2 7*8*32=1792
#define OFF_W1    0
#define OFF_W2    13312
#define OFF_FUSED 16224
#define OFF_C1    22048
#define OFF_C2    24960

// ---------------- helpers ----------------
__device__ __forceinline__ uint32_t smem_u32(const void* p) {
    uint32_t a;
    asm("{ .reg .u64 t; cvta.to.shared.u64 t, %1; cvt.u32.u64 %0, t; }"
        : "=r"(a) : "l"(p));
    return a;
}
__device__ __forceinline__ uint32_t sw128(uint32_t off) {
    return off ^ ((off >> 3) & 0x70);
}
__device__ __forceinline__ uint32_t packh2(float lo, float hi) {
    __half2 h = __floats2half2_rn(lo, hi);
    return *reinterpret_cast<uint32_t*>(&h);
}
__device__ __forceinline__ uint32_t packbf2(float lo, float hi) {
    __nv_bfloat162 h = __floats2bfloat162_rn(lo, hi);
    return *reinterpret_cast<uint32_t*>(&h);
}
// truncation split: h = {hi16(a), hi16(b)}, l = bf16 residuals (exact residual)
__device__ __forceinline__ void csplit(float a, float b, uint32_t& h, uint32_t& l) {
    uint32_t ab = __float_as_uint(a), bb = __float_as_uint(b);
    asm("prmt.b32 %0, %1, %2, 0x7632;" : "=r"(h) : "r"(ab), "r"(bb));
    float ra = a - __uint_as_float(ab & 0xffff0000u);
    float rb = b - __uint_as_float(bb & 0xffff0000u);
    l = packbf2(ra, rb);
}
__device__ __forceinline__ void ldm_x4(uint32_t& r0, uint32_t& r1, uint32_t& r2,
                                       uint32_t& r3, uint32_t addr) {
    asm volatile("ldmatrix.sync.aligned.m8n8.x4.shared.b16 {%0,%1,%2,%3}, [%4];"
                 : "=r"(r0), "=r"(r1), "=r"(r2), "=r"(r3) : "r"(addr));
}
__device__ __forceinline__ void mma_bf16(float* d, uint32_t a0, uint32_t a1,
                                         uint32_t a2, uint32_t a3,
                                         uint32_t b0, uint32_t b1) {
    asm volatile(
        "mma.sync.aligned.m16n8k16.row.col.f32.bf16.bf16.f32 "
        "{%0,%1,%2,%3}, {%4,%5,%6,%7}, {%8,%9}, {%0,%1,%2,%3};"
        : "+f"(d[0]), "+f"(d[1]), "+f"(d[2]), "+f"(d[3])
        : "r"(a0), "r"(a1), "r"(a2), "r"(a3), "r"(b0), "r"(b1));
}
__device__ __forceinline__ void mma_fp16(float* d, uint32_t a0, uint32_t a1,
                                         uint32_t a2, uint32_t a3,
                                         uint32_t b0, uint32_t b1) {
    asm volatile(
        "mma.sync.aligned.m16n8k16.row.col.f32.f16.f16.f32 "
        "{%0,%1,%2,%3}, {%4,%5,%6,%7}, {%8,%9}, {%0,%1,%2,%3};"
        : "+f"(d[0]), "+f"(d[1]), "+f"(d[2]), "+f"(d[3])
        : "r"(a0), "r"(a1), "r"(a2), "r"(a3), "r"(b0), "r"(b1));
}

// ---------------- single merged B-fragment pre-pack ----------------
__global__ void wfrag_all(const float* __restrict__ W1, const float* __restrict__ W2,
                          const float* __restrict__ WR, const float* __restrict__ WS,
                          const float* __restrict__ C1, const float* __restrict__ C2,
                          uint4* __restrict__ out)
{
    int idx = blockIdx.x * blockDim.x + threadIdx.x;
    if (idx >= 26752) return;
    const float* W; int K, NOUT, NTC, NTT, NTO, base; bool f16;
    if (idx < 13312)      { W=W1; K=500; NOUT=100; NTC=13; NTT=13; NTO=0;  base=OFF_W1;    f16=true;  }
    else if (idx < 16224) { idx-=13312; W=W2; K=100; NOUT=100; NTC=13; NTT=13; NTO=0;  base=OFF_W2;    f16=false; }
    else if (idx < 19136) { idx-=16224; W=WR; K=100; NOUT=100; NTC=13; NTT=26; NTO=0;  base=OFF_FUSED; f16=false; }
    else if (idx < 22048) { idx-=19136; W=WS; K=100; NOUT=100; NTC=13; NTT=26; NTO=13; base=OFF_FUSED; f16=false; }
    else if (idx < 24960) { idx-=22048; W=C1; K=100; NOUT=100; NTC=13; NTT=13; NTO=0;  base=OFF_C1;    f16=false; }
    else                  { idx-=24960; W=C2; K=100; NOUT=64;  NTC=8;  NTT=8;  NTO=0;  base=OFF_C2;    f16=false; }

    int lane = idx & 31, nt = (idx >> 5) % NTC, ks = idx / (32 * NTC);
    int n  = nt * 8 + (lane >> 2);
    int k0 = ks * 16 + (lane & 3) * 2;
    float w[4]; int kk[4] = {k0, k0 + 1, k0 + 8, k0 + 9};
    #pragma unroll
    for (int i = 0; i < 4; i++)
        w[i] = (kk[i] < K && n < NOUT) ? W[(size_t)kk[i] * NOUT + n] : 0.0f;

    uint4 o;
    if (f16) {
        float hi[4], lo[4];
        #pragma unroll
        for (int i = 0; i < 4; i++) {
            hi[i] = __half2float(__float2half_rn(w[i]));
            lo[i] = w[i] - hi[i];
        }
        o = make_uint4(packh2(hi[0], hi[1]), packh2(hi[2], hi[3]),
                       packh2(lo[0], lo[1]), packh2(lo[2], lo[3]));
    } else {
        float hi[4], lo[4];
        #pragma unroll
        for (int i = 0; i < 4; i++) {
            hi[i] = __bfloat162float(__float2bfloat16(w[i]));
            lo[i] = w[i] - hi[i];
        }
        o = make_uint4(packbf2(hi[0], hi[1]), packbf2(hi[2], hi[3]),
                       packbf2(lo[0], lo[1]), packbf2(lo[2], lo[3]));
    }
    out[base + ((size_t)ks * NTT + NTO + nt) * 32 + lane] = o;
}

// ---------------- unified mma GEMM ----------------
// AMODE 0: A fp32 -> fp16 convert-stage, 2-term mma (hi, lo from W only)
// AMODE 1: A pre-split bf16 planes, copy-stage, 3-term mma
// EPI 1: +bias, LayerNorm, ReLU -> split planes OH/OL
// EPI 2: *dinv[row] -> fp32 out
// EPI 3: dual out: nt<13 -> out (msg), nt>=13 -> out2 + bias (self)
template <int AMODE, int KPAD, int KVALID, int KSTEPS, int NT8, int NOUT, int EPI>
__global__ void __launch_bounds__(256) gemm_mma(
    const float* __restrict__ A,
    const __nv_bfloat16* __restrict__ AH, const __nv_bfloat16* __restrict__ AL,
    const uint4* __restrict__ WF,
    const float* __restrict__ bias, const float* __restrict__ gamma,
    const float* __restrict__ beta, const float* __restrict__ dinv,
    float* __restrict__ out, float* __restrict__ out2,
    __nv_bfloat16* __restrict__ OH, __nv_bfloat16* __restrict__ OL, int M)
{
    extern __shared__ char rawsm[];
    char* smem = (char*)(((uintptr_t)rawsm + 1023) & ~(uintptr_t)1023);
    const uint32_t abase = smem_u32(smem);
    constexpr int SM_AL = 16384;
    constexpr int NCHUNK = (KSTEPS + 3) / 4;

    const int tid = threadIdx.x, wid = tid >> 5, lane = tid & 31;
    const int row0 = blockIdx.x * 128;

    float acc[NT8][4];
    #pragma unroll
    for (int nt = 0; nt < NT8; nt++)
        #pragma unroll
        for (int j = 0; j < 4; j++) acc[nt][j] = 0.0f;

    const uint32_t a_off0 =
        (uint32_t)((wid * 16 + (lane & 15)) * 128 + (lane >> 4) * 16);

    for (int c0 = 0; c0 < NCHUNK; c0++) {
        const int k0 = c0 * 64;
        if constexpr (AMODE == 0) {
            // fp32 -> fp16 convert staging (single plane)
            #pragma unroll
            for (int u0 = 0; u0 < 1024; u0 += 256) {
                int u = u0 + tid;
                int m = u >> 3, cc = u & 7;
                int grow = row0 + m;
                int k = k0 + cc * 8;
                float x0=0.f,x1=0.f,x2=0.f,x3=0.f,x4=0.f,x5=0.f,x6=0.f,x7=0.f;
                if (grow < M) {
                    const float* ap = A + (size_t)grow * KVALID + k;
                    if (k < KVALID)     { float4 f = __ldg((const float4*)ap);
                                          x0=f.x; x1=f.y; x2=f.z; x3=f.w; }
                    if (k + 4 < KVALID) { float4 f = __ldg((const float4*)(ap + 4));
                                          x4=f.x; x5=f.y; x6=f.z; x7=f.w; }
                }
                uint4 h;
                h.x = packh2(x0, x1); h.y = packh2(x2, x3);
                h.z = packh2(x4, x5); h.w = packh2(x6, x7);
                *(uint4*)(smem + sw128((uint32_t)(m * 128 + cc * 16))) = h;
            }
        } else {
            // copy staging of pre-split planes
            #pragma unroll
            for (int u0 = 0; u0 < 1024; u0 += 256) {
                int u = u0 + tid;
                int m = u >> 3, cc = u & 7;
                int grow = row0 + m;
                int k = k0 + cc * 8;
                uint4 h = make_uint4(0,0,0,0), l = make_uint4(0,0,0,0);
                if (grow < M && k < KVALID) {
                    h = *(const uint4*)(AH + (size_t)grow * KPAD + k);
                    l = *(const uint4*)(AL + (size_t)grow * KPAD + k);
                }
                uint32_t off = sw128((uint32_t)(m * 128 + cc * 16));
                *(uint4*)(smem + off)         = h;
                *(uint4*)(smem + SM_AL + off) = l;
            }
        }
        __syncthreads();

        const int nks = (KSTEPS - c0 * 4 < 4) ? (KSTEPS - c0 * 4) : 4;
        for (int ks = 0; ks < nks; ks++) {
            uint32_t off = sw128(a_off0 + (uint32_t)(ks * 32));
            uint32_t ah0, ah1, ah2, ah3;
            ldm_x4(ah0, ah1, ah2, ah3, abase + off);
            uint32_t al0, al1, al2, al3;
            if constexpr (AMODE == 1)
                ldm_x4(al0, al1, al2, al3, abase + SM_AL + off);
            const uint4* wp = WF + (size_t)(c0 * 4 + ks) * NT8 * 32 + lane;
            #pragma unroll
            for (int nt = 0; nt < NT8; nt++) {
                uint4 f = __ldg(wp + nt * 32);
                if constexpr (AMODE == 0) {
                    mma_fp16(acc[nt], ah0, ah1, ah2, ah3, f.x, f.y);
                    mma_fp16(acc[nt], ah0, ah1, ah2, ah3, f.z, f.w);
                } else {
                    mma_bf16(acc[nt], ah0, ah1, ah2, ah3, f.x, f.y);
                    mma_bf16(acc[nt], al0, al1, al2, al3, f.x, f.y);
                    mma_bf16(acc[nt], ah0, ah1, ah2, ah3, f.z, f.w);
                }
            }
        }
        __syncthreads();
    }

    // ---- epilogue ----
    const int r0 = row0 + wid * 16 + (lane >> 2);
    const int r1 = r0 + 8;
    const int cbase = (lane & 3) * 2;

    if constexpr (EPI == 1) {
        float s0 = 0.f, q0 = 0.f, s1 = 0.f, q1 = 0.f;
        #pragma unroll
        for (int nt = 0; nt < NT8; nt++) {
            int n0 = nt * 8 + cbase;
            float b0 = 0.f, b1 = 0.f;
            if (n0 < NOUT) { float2 bb = *(const float2*)(bias + n0); b0 = bb.x; b1 = bb.y; }
            float t;
            t = acc[nt][0] + b0; acc[nt][0] = t; s0 += t; q0 += t * t;
            t = acc[nt][1] + b1; acc[nt][1] = t; s0 += t; q0 += t * t;
            t = acc[nt][2] + b0; acc[nt][2] = t; s1 += t; q1 += t * t;
            t = acc[nt][3] + b1; acc[nt][3] = t; s1 += t; q1 += t * t;
        }
        #pragma unroll
        for (int o = 1; o <= 2; o <<= 1) {
            s0 += __shfl_xor_sync(0xffffffffu, s0, o);
            q0 += __shfl_xor_sync(0xffffffffu, q0, o);
            s1 += __shfl_xor_sync(0xffffffffu, s1, o);
            q1 += __shfl_xor_sync(0xffffffffu, q1, o);
        }
        float mu0 = s0 * (1.0f / NOUT), mu1 = s1 * (1.0f / NOUT);
        float rs0 = rsqrtf(q0 * (1.0f / NOUT) - mu0 * mu0 + LN_EPS);
        float rs1 = rsqrtf(q1 * (1.0f / NOUT) - mu1 * mu1 + LN_EPS);
        #pragma unroll
        for (int nt = 0; nt < NT8; nt++) {
            int n0 = nt * 8 + cbase;
            bool valid = n0 < NOUT;
            float v0 = 0.f, v1 = 0.f, v2 = 0.f, v3 = 0.f;
            if (valid) {
                float2 gg = *(const float2*)(gamma + n0);
                float2 bb = *(const float2*)(beta + n0);
                v0 = fmaxf(0.f, (acc[nt][0] - mu0) * rs0 * gg.x + bb.x);
                v1 = fmaxf(0.f, (acc[nt][1] - mu0) * rs0 * gg.y + bb.y);
                v2 = fmaxf(0.f, (acc[nt][2] - mu1) * rs1 * gg.x + bb.x);
                v3 = fmaxf(0.f, (acc[nt][3] - mu1) * rs1 * gg.y + bb.y);
            }
            uint32_t h, l;
            if (r0 < M) {
                csplit(v0, v1, h, l);
                if (!valid) { h = 0u; l = 0u; }
                *(uint32_t*)(OH + (size_t)r0 * 128 + n0) = h;
                *(uint32_t*)(OL + (size_t)r0 * 128 + n0) = l;
            }
            if (r1 < M) {
                csplit(v2, v3, h, l);
                if (!valid) { h = 0u; l = 0u; }
                *(uint32_t*)(OH + (size_t)r1 * 128 + n0) = h;
                *(uint32_t*)(OL + (size_t)r1 * 128 + n0) = l;
            }
        }
    } else if constexpr (EPI == 2) {
        float d0 = (r0 < M) ? dinv[r0] : 0.f;
        float d1 = (r1 < M) ? dinv[r1] : 0.f;
        #pragma unroll
        for (int nt = 0; nt < NT8; nt++) {
            int n0 = nt * 8 + cbase;
            if (n0 < NOUT) {
                if (r0 < M)
                    *(float2*)(out + (size_t)r0 * NOUT + n0) =
                        make_float2(acc[nt][0] * d0, acc[nt][1] * d0);
                if (r1 < M)
                    *(float2*)(out + (size_t)r1 * NOUT + n0) =
                        make_float2(acc[nt][2] * d1, acc[nt][3] * d1);
            }
        }
    } else {  // EPI == 3: dual output (msg, self+bias)
        constexpr int NTH = NT8 / 2;
        #pragma unroll
        for (int nt = 0; nt < NTH; nt++) {
            int n0 = nt * 8 + cbase;
            if (n0 < NOUT) {
                if (r0 < M)
                    *(float2*)(out + (size_t)r0 * NOUT + n0) =
                        make_float2(acc[nt][0], acc[nt][1]);
                if (r1 < M)
                    *(float2*)(out + (size_t)r1 * NOUT + n0) =
                        make_float2(acc[nt][2], acc[nt][3]);
            }
        }
        #pragma unroll
        for (int nt = NTH; nt < NT8; nt++) {
            int n0 = (nt - NTH) * 8 + cbase;
            if (n0 < NOUT) {
                float2 bb = *(const float2*)(bias + n0);
                if (r0 < M)
                    *(float2*)(out2 + (size_t)r0 * NOUT + n0) =
                        make_float2(acc[nt][0] + bb.x, acc[nt][1] + bb.y);
                if (r1 < M)
                    *(float2*)(out2 + (size_t)r1 * NOUT + n0) =
                        make_float2(acc[nt][2] + bb.x, acc[nt][3] + bb.y);
            }
        }
    }
}

// ---------------- CSR construction ----------------
__global__ void zero_cnt_kernel() {
    int i = blockIdx.x * blockDim.x + threadIdx.x;
    if (i < NN) g_cnt[i] = 0;
}
__global__ void count_kernel(const int* __restrict__ tgt) {
    int e = blockIdx.x * blockDim.x + threadIdx.x;
    if (e < EE) atomicAdd(&g_cnt[tgt[e]], 1);
}
__global__ void scan_kernel() {
    __shared__ int ws[32];
    __shared__ int base_s;
    int tid = threadIdx.x, lane = tid & 31, w = tid >> 5;
    if (tid == 0) base_s = 0;
    __syncthreads();
    for (int b0 = 0; b0 < NN; b0 += 1024) {
        int i = b0 + tid;
        int v = (i < NN) ? g_cnt[i] : 0;
        int x = v;
        #pragma unroll
        for (int o = 1; o < 32; o <<= 1) {
            int t = __shfl_up_sync(0xffffffffu, x, o);
            if (lane >= o) x += t;
        }
        if (lane == 31) ws[w] = x;
        __syncthreads();
        if (w == 0) {
            int y = ws[lane];
            #pragma unroll
            for (int o = 1; o < 32; o <<= 1) {
                int t = __shfl_up_sync(0xffffffffu, y, o);
                if (lane >= o) y += t;
            }
            ws[lane] = y;
        }
        __syncthreads();
        int ex = base_s + ((w > 0) ? ws[w - 1] : 0) + x - v;
        if (i < NN) { g_rowptr[i] = ex; g_cur[i] = ex; }
        int tot = ws[31];
        __syncthreads();
        if (tid == 0) base_s += tot;
        __syncthreads();
    }
    if (tid == 0) g_rowptr[NN] = base_s;
}
__global__ void fill_kernel(const int* __restrict__ src, const int* __restrict__ tgt) {
    int e = blockIdx.x * blockDim.x + threadIdx.x;
    if (e < EE) {
        int pos = atomicAdd(&g_cur[tgt[e]], 1);
        g_csr[pos] = src[e];
    }
}
__global__ void dinv_kernel() {
    int i = blockIdx.x * blockDim.x + threadIdx.x;
    if (i < NN) g_dinv[i] = rsqrtf((float)(g_cnt[i] + 1));
}

// ---------------- gather: out[v] = epi(init[v] + sum_{e: tgt=v} msg[src_e]) -----
// MODE 0: relu                  MODE 1: *dinv[v]+bias, relu   MODE 2: *dinv+bias, log_softmax
// SOUT: write truncation-split bf16 planes instead of fp32
template <int C, int MODE, bool SOUT>
__global__ void gather_kernel(const float* __restrict__ msg,
                              const float* __restrict__ init,
                              const float* __restrict__ bias,
                              float* __restrict__ out,
                              __nv_bfloat16* __restrict__ OH,
                              __nv_bfloat16* __restrict__ OL)
{
    int warp = (blockIdx.x * blockDim.x + threadIdx.x) >> 5;
    int lane = threadIdx.x & 31;
    if (warp >= NN) return;
    constexpr int C4 = C / 4;
    bool act = lane < C4;

    float4 acc = make_float4(0.f, 0.f, 0.f, 0.f);
    if (act) acc = __ldg((const float4*)(init + (long long)warp * C) + lane);

    int beg = g_rowptr[warp];
    int end = g_rowptr[warp + 1];
    int e = beg;
    for (; e + 1 < end; e += 2) {
        int s0 = g_csr[e];
        int s1 = g_csr[e + 1];
        if (act) {
            float4 t0 = __ldg((const float4*)(msg + (long long)s0 * C) + lane);
            float4 t1 = __ldg((const float4*)(msg + (long long)s1 * C) + lane);
            acc.x += t0.x + t1.x; acc.y += t0.y + t1.y;
            acc.z += t0.z + t1.z; acc.w += t0.w + t1.w;
        }
    }
    if (e < end) {
        int s0 = g_csr[e];
        if (act) {
            float4 t0 = __ldg((const float4*)(msg + (long long)s0 * C) + lane);
            acc.x += t0.x; acc.y += t0.y; acc.z += t0.z; acc.w += t0.w;
        }
    }

    float4 t = make_float4(0.f, 0.f, 0.f, 0.f);
    if (MODE == 0) {
        t = make_float4(fmaxf(0.f, acc.x), fmaxf(0.f, acc.y),
                        fmaxf(0.f, acc.z), fmaxf(0.f, acc.w));
    } else {
        float d = g_dinv[warp];
        if (act) {
            float4 b4 = __ldg((const float4*)bias + lane);
            t.x = acc.x * d + b4.x; t.y = acc.y * d + b4.y;
            t.z = acc.z * d + b4.z; t.w = acc.w * d + b4.w;
        }
        if (MODE == 1) {
            t = make_float4(fmaxf(0.f, t.x), fmaxf(0.f, t.y),
                            fmaxf(0.f, t.z), fmaxf(0.f, t.w));
        }
    }

    if (MODE == 2) {
        float m = act ? fmaxf(fmaxf(t.x, t.y), fmaxf(t.z, t.w)) : -1e30f;
        #pragma unroll
        for (int o = 16; o; o >>= 1) m = fmaxf(m, __shfl_xor_sync(0xffffffffu, m, o));
        float se = act ? (expf(t.x - m) + expf(t.y - m) + expf(t.z - m) + expf(t.w - m))
                       : 0.0f;
        #pragma unroll
        for (int o = 16; o; o >>= 1) se += __shfl_xor_sync(0xffffffffu, se, o);
        float lse = logf(se);
        if (act) {
            float4 r = make_float4(t.x - m - lse, t.y - m - lse,
                                   t.z - m - lse, t.w - m - lse);
            *((float4*)(out + (long long)warp * C) + lane) = r;
        }
    } else if (SOUT) {
        uint32_t h0 = 0, l0 = 0, h1 = 0, l1 = 0;
        if (act) { csplit(t.x, t.y, h0, l0); csplit(t.z, t.w, h1, l1); }
        if (lane <= C4) {   // lane C4 pads cols [C, C+4) with zeros
            *(uint2*)(OH + (size_t)warp * 128 + lane * 4) = make_uint2(h0, h1);
            *(uint2*)(OL + (size_t)warp * 128 + lane * 4) = make_uint2(l0, l1);
        }
    } else {
        if (act) *((float4*)(out + (long long)warp * C) + lane) = t;
    }
}

// ---------------- launcher ----------------
extern "C" void kernel_launch(void* const* d_in, const int* in_sizes, int n_in,
                              void* d_out, int out_size)
{
    const float* X     = (const float*)d_in[0];
    const int*   EI    = (const int*)d_in[1];
    const float* W1    = (const float*)d_in[3];
    const float* b1    = (const float*)d_in[4];
    const float* g1    = (const float*)d_in[5];
    const float* be1   = (const float*)d_in[6];
    const float* W2    = (const float*)d_in[7];
    const float* b2    = (const float*)d_in[8];
    const float* g2    = (const float*)d_in[9];
    const float* be2   = (const float*)d_in[10];
    const float* Wrel  = (const float*)d_in[11];
    const float* Wself = (const float*)d_in[12];
    const float* rb    = (const float*)d_in[13];
    const float* c1W   = (const float*)d_in[14];
    const float* c1b   = (const float*)d_in[15];
    const float* c2W   = (const float*)d_in[16];
    const float* c2b   = (const float*)d_in[17];

    const int* src = EI;
    const int* tgt = EI + EE;

    float *buf1, *buf3, *buf4, *dinvp;
    __nv_bfloat16 *sp1, *sp2;
    uint4* wf;
    cudaGetSymbolAddress((void**)&buf1, g_buf1);
    cudaGetSymbolAddress((void**)&buf3, g_buf3);
    cudaGetSymbolAddress((void**)&buf4, g_buf4);
    cudaGetSymbolAddress((void**)&dinvp, g_dinv);
    cudaGetSymbolAddress((void**)&sp1, g_sp1);
    cudaGetSymbolAddress((void**)&sp2, g_sp2);
    cudaGetSymbolAddress((void**)&wf, g_wfrag);

    __nv_bfloat16* s1H = sp1;
    __nv_bfloat16* s1L = sp1 + (size_t)NN * 128;
    __nv_bfloat16* s2H = sp2;
    __nv_bfloat16* s2L = sp2 + (size_t)NN * 128;

    // --- B-fragment pre-pack (one launch) ---
    wfrag_all<<<(26752 + 255) / 256, 256>>>(W1, W2, Wrel, Wself, c1W, c2W, wf);

    // --- CSR + degrees ---
    zero_cnt_kernel<<<(NN + 255) / 256, 256>>>();
    count_kernel<<<(EE + 255) / 256, 256>>>(tgt);
    scan_kernel<<<1, 1024>>>();
    fill_kernel<<<(EE + 255) / 256, 256>>>(src, tgt);
    dinv_kernel<<<(NN + 255) / 256, 256>>>();

    const int MB = (NN + 127) / 128;     // 391
    const int WB = (NN + 7) / 8;         // gather blocks (256 thr, warp/node)
    const int SMEM_H  = 16384 + 1024;    // fp16 convert-stage
    const int SMEM_BF = 32768 + 1024;    // bf16 copy-stage

    // --- GEMM1: X @ W1 (fp16 2-term) + LN + ReLU -> split s1 ---
    gemm_mma<0, 512, DIN, 32, 13, HID, 1><<<MB, 256, SMEM_H>>>(
        X, nullptr, nullptr, wf + OFF_W1, b1, g1, be1, nullptr,
        nullptr, nullptr, s1H, s1L, NN);
    // --- GEMM2: s1 @ W2 + LN + ReLU -> split s2 ---
    gemm_mma<1, 128, 104, 7, 13, HID, 1><<<MB, 256, SMEM_BF>>>(
        nullptr, s1H, s1L, wf + OFF_W2, b2, g2, be2, nullptr,
        nullptr, nullptr, s2H, s2L, NN);

    // --- RGCN fused: msg = s2@Wrel -> buf3, self = s2@Wself + rb -> buf4 ---
    gemm_mma<1, 128, 104, 7, 26, HID, 3><<<MB, 256, SMEM_BF>>>(
        nullptr, s2H, s2L, wf + OFF_FUSED, rb, nullptr, nullptr, nullptr,
        buf3, buf4, nullptr, nullptr, NN);
    gather_kernel<HID, 0, true><<<WB, 256>>>(buf3, buf4, nullptr, nullptr, s1H, s1L);

    // --- GCNConv 1: hs = (x@c1W)*dinv -> buf1; gather -> split s2 ---
    gemm_mma<1, 128, 104, 7, 13, HID, 2><<<MB, 256, SMEM_BF>>>(
        nullptr, s1H, s1L, wf + OFF_C1, nullptr, nullptr, nullptr, dinvp,
        buf1, nullptr, nullptr, nullptr, NN);
    gather_kernel<HID, 1, true><<<WB, 256>>>(buf1, buf1, c1b, nullptr, s2H, s2L);

    // --- GCNConv 2 (100->64) + log_softmax ---
    gemm_mma<1, 128, 104, 7, 8, DOUT, 2><<<MB, 256, SMEM_BF>>>(
        nullptr, s2H, s2L, wf + OFF_C2, nullptr, nullptr, nullptr, dinvp,
        buf4, nullptr, nullptr, nullptr, NN);
    gather_kernel<DOUT, 2, false><<<WB, 256>>>(buf4, buf4, c2b, (float*)d_out,
                                               nullptr, nullptr);
}

// round 9
// speedup vs baseline: 2.2731x; 1.0972x over previous
#include <cuda_runtime.h>
#include <cuda_fp16.h>
#include <cstdint>

#define NN   50000
#define EE   800000
#define DIN  500
#define HID  100
#define DOUT 64
#define LN_EPS 1e-5f
#define NBLK 49   // ceil(NN/1024)

// ---------------- scratch (static device globals: allowed) ----------------
__device__ __half g_hp1[NN * 128];
__device__ __half g_hp2[NN * 128];
__device__ __half g_hp3[NN * 128];
__device__ float g_self[NN * HID];
__device__ int   g_cnt[NN];
__device__ int   g_rowptr[NN + 1];
__device__ int   g_cur[NN];
__device__ int   g_csr[EE];
__device__ float g_dinv[NN];
__device__ int   g_bsum[64];
__device__ int   g_boff[64];
// pre-packed per-lane B fragments (fp16 hi/lo pairs)
__device__ uint4 g_wfrag[26752];

// wfrag offsets (uint4): W1 32*13*32=13312 | W2 2912 | FUSED(rel+self) 5824 | C1 2912 | C2 1792
#define OFF_W1    0
#define OFF_W2    13312
#define OFF_FUSED 16224
#define OFF_C1    22048
#define OFF_C2    24960

// ---------------- helpers ----------------
__device__ __forceinline__ uint32_t smem_u32(const void* p) {
    uint32_t a;
    asm("{ .reg .u64 t; cvta.to.shared.u64 t, %1; cvt.u32.u64 %0, t; }"
        : "=r"(a) : "l"(p));
    return a;
}
__device__ __forceinline__ uint32_t sw128(uint32_t off) {
    return off ^ ((off >> 3) & 0x70);
}
__device__ __forceinline__ uint32_t packh2(float lo, float hi) {
    __half2 h = __floats2half2_rn(lo, hi);
    return *reinterpret_cast<uint32_t*>(&h);
}
__device__ __forceinline__ void ldm_x4(uint32_t& r0, uint32_t& r1, uint32_t& r2,
                                       uint32_t& r3, uint32_t addr) {
    asm volatile("ldmatrix.sync.aligned.m8n8.x4.shared.b16 {%0,%1,%2,%3}, [%4];"
                 : "=r"(r0), "=r"(r1), "=r"(r2), "=r"(r3) : "r"(addr));
}
__device__ __forceinline__ void mma_fp16(float* d, uint32_t a0, uint32_t a1,
                                         uint32_t a2, uint32_t a3,
                                         uint32_t b0, uint32_t b1) {
    asm volatile(
        "mma.sync.aligned.m16n8k16.row.col.f32.f16.f16.f32 "
        "{%0,%1,%2,%3}, {%4,%5,%6,%7}, {%8,%9}, {%0,%1,%2,%3};"
        : "+f"(d[0]), "+f"(d[1]), "+f"(d[2]), "+f"(d[3])
        : "r"(a0), "r"(a1), "r"(a2), "r"(a3), "r"(b0), "r"(b1));
}
__device__ __forceinline__ void acc8(float* acc, uint4 v) {
    const __half2* h = (const __half2*)&v;
    #pragma unroll
    for (int i = 0; i < 4; i++) {
        float2 f = __half22float2(h[i]);
        acc[2 * i]     += f.x;
        acc[2 * i + 1] += f.y;
    }
}

// ---------------- merged B-fragment pre-pack (all fp16 hi/lo) ----------------
__global__ void wfrag_all(const float* __restrict__ W1, const float* __restrict__ W2,
                          const float* __restrict__ WR, const float* __restrict__ WS,
                          const float* __restrict__ C1, const float* __restrict__ C2,
                          uint4* __restrict__ out)
{
    int idx = blockIdx.x * blockDim.x + threadIdx.x;
    if (idx >= 26752) return;
    const float* W; int K, NOUT, NTC, NTT, NTO, base;
    if (idx < 13312)      { W=W1; K=500; NOUT=100; NTC=13; NTT=13; NTO=0;  base=OFF_W1;    }
    else if (idx < 16224) { idx-=13312; W=W2; K=100; NOUT=100; NTC=13; NTT=13; NTO=0;  base=OFF_W2;    }
    else if (idx < 19136) { idx-=16224; W=WR; K=100; NOUT=100; NTC=13; NTT=26; NTO=0;  base=OFF_FUSED; }
    else if (idx < 22048) { idx-=19136; W=WS; K=100; NOUT=100; NTC=13; NTT=26; NTO=13; base=OFF_FUSED; }
    else if (idx < 24960) { idx-=22048; W=C1; K=100; NOUT=100; NTC=13; NTT=13; NTO=0;  base=OFF_C1;    }
    else                  { idx-=24960; W=C2; K=100; NOUT=64;  NTC=8;  NTT=8;  NTO=0;  base=OFF_C2;    }

    int lane = idx & 31, nt = (idx >> 5) % NTC, ks = idx / (32 * NTC);
    int n  = nt * 8 + (lane >> 2);
    int k0 = ks * 16 + (lane & 3) * 2;
    float w[4]; int kk[4] = {k0, k0 + 1, k0 + 8, k0 + 9};
    #pragma unroll
    for (int i = 0; i < 4; i++)
        w[i] = (kk[i] < K && n < NOUT) ? W[(size_t)kk[i] * NOUT + n] : 0.0f;

    float hi[4], lo[4];
    #pragma unroll
    for (int i = 0; i < 4; i++) {
        hi[i] = __half2float(__float2half_rn(w[i]));
        lo[i] = w[i] - hi[i];
    }
    out[base + ((size_t)ks * NTT + NTO + nt) * 32 + lane] =
        make_uint4(packh2(hi[0], hi[1]), packh2(hi[2], hi[3]),
                   packh2(lo[0], lo[1]), packh2(lo[2], lo[3]));
}

// ---------------- unified fp16 mma GEMM ----------------
// AMODE 0: A fp32 -> fp16 convert-stage (GEMM1)   AMODE 1: A fp16 plane copy-stage
// EPI 1: +bias, LayerNorm, ReLU -> fp16 plane OH
// EPI 2: *dinv[row]            -> fp16 plane OH
// EPI 3: dual: nt<13 -> OH fp16 (msg), nt>=13 -> out2 fp32 (+bias) (self)
template <int AMODE, int KVALID, int KSTEPS, int NT8, int NOUT, int EPI>
__global__ void __launch_bounds__(256) gemm_mma(
    const float* __restrict__ A, const __half* __restrict__ AH,
    const uint4* __restrict__ WF,
    const float* __restrict__ bias, const float* __restrict__ gamma,
    const float* __restrict__ beta, const float* __restrict__ dinv,
    float* __restrict__ out2, __half* __restrict__ OH, int M)
{
    extern __shared__ char rawsm[];
    char* smem = (char*)(((uintptr_t)rawsm + 1023) & ~(uintptr_t)1023);
    const uint32_t abase = smem_u32(smem);
    constexpr int NCHUNK = (KSTEPS + 3) / 4;

    const int tid = threadIdx.x, wid = tid >> 5, lane = tid & 31;
    const int row0 = blockIdx.x * 128;

    float acc[NT8][4];
    #pragma unroll
    for (int nt = 0; nt < NT8; nt++)
        #pragma unroll
        for (int j = 0; j < 4; j++) acc[nt][j] = 0.0f;

    const uint32_t a_off0 =
        (uint32_t)((wid * 16 + (lane & 15)) * 128 + (lane >> 4) * 16);

    for (int c0 = 0; c0 < NCHUNK; c0++) {
        const int k0 = c0 * 64;
        if constexpr (AMODE == 0) {
            #pragma unroll
            for (int u0 = 0; u0 < 1024; u0 += 256) {
                int u = u0 + tid;
                int m = u >> 3, cc = u & 7;
                int grow = row0 + m;
                int k = k0 + cc * 8;
                float x0=0.f,x1=0.f,x2=0.f,x3=0.f,x4=0.f,x5=0.f,x6=0.f,x7=0.f;
                if (grow < M) {
                    const float* ap = A + (size_t)grow * KVALID + k;
                    if (k < KVALID)     { float4 f = __ldg((const float4*)ap);
                                          x0=f.x; x1=f.y; x2=f.z; x3=f.w; }
                    if (k + 4 < KVALID) { float4 f = __ldg((const float4*)(ap + 4));
                                          x4=f.x; x5=f.y; x6=f.z; x7=f.w; }
                }
                uint4 h;
                h.x = packh2(x0, x1); h.y = packh2(x2, x3);
                h.z = packh2(x4, x5); h.w = packh2(x6, x7);
                *(uint4*)(smem + sw128((uint32_t)(m * 128 + cc * 16))) = h;
            }
        } else {
            #pragma unroll
            for (int u0 = 0; u0 < 1024; u0 += 256) {
                int u = u0 + tid;
                int m = u >> 3, cc = u & 7;
                int grow = row0 + m;
                int k = k0 + cc * 8;
                uint4 h = make_uint4(0, 0, 0, 0);
                if (grow < M && k < KVALID)
                    h = *(const uint4*)(AH + (size_t)grow * 128 + k);
                *(uint4*)(smem + sw128((uint32_t)(m * 128 + cc * 16))) = h;
            }
        }
        __syncthreads();

        const int nks = (KSTEPS - c0 * 4 < 4) ? (KSTEPS - c0 * 4) : 4;
        for (int ks = 0; ks < nks; ks++) {
            uint32_t off = sw128(a_off0 + (uint32_t)(ks * 32));
            uint32_t a0, a1, a2, a3;
            ldm_x4(a0, a1, a2, a3, abase + off);
            const uint4* wp = WF + (size_t)(c0 * 4 + ks) * NT8 * 32 + lane;
            #pragma unroll
            for (int nt = 0; nt < NT8; nt++) {
                uint4 f = __ldg(wp + nt * 32);
                mma_fp16(acc[nt], a0, a1, a2, a3, f.x, f.y);
                mma_fp16(acc[nt], a0, a1, a2, a3, f.z, f.w);
            }
        }
        __syncthreads();
    }

    // ---- epilogue ----
    const int r0 = row0 + wid * 16 + (lane >> 2);
    const int r1 = r0 + 8;
    const int cbase = (lane & 3) * 2;

    if constexpr (EPI == 1) {
        float s0 = 0.f, q0 = 0.f, s1 = 0.f, q1 = 0.f;
        #pragma unroll
        for (int nt = 0; nt < NT8; nt++) {
            int n0 = nt * 8 + cbase;
            float b0 = 0.f, b1 = 0.f;
            if (n0 < NOUT) { float2 bb = *(const float2*)(bias + n0); b0 = bb.x; b1 = bb.y; }
            float t;
            t = acc[nt][0] + b0; acc[nt][0] = t; s0 += t; q0 += t * t;
            t = acc[nt][1] + b1; acc[nt][1] = t; s0 += t; q0 += t * t;
            t = acc[nt][2] + b0; acc[nt][2] = t; s1 += t; q1 += t * t;
            t = acc[nt][3] + b1; acc[nt][3] = t; s1 += t; q1 += t * t;
        }
        #pragma unroll
        for (int o = 1; o <= 2; o <<= 1) {
            s0 += __shfl_xor_sync(0xffffffffu, s0, o);
            q0 += __shfl_xor_sync(0xffffffffu, q0, o);
            s1 += __shfl_xor_sync(0xffffffffu, s1, o);
            q1 += __shfl_xor_sync(0xffffffffu, q1, o);
        }
        float mu0 = s0 * (1.0f / NOUT), mu1 = s1 * (1.0f / NOUT);
        float rs0 = rsqrtf(q0 * (1.0f / NOUT) - mu0 * mu0 + LN_EPS);
        float rs1 = rsqrtf(q1 * (1.0f / NOUT) - mu1 * mu1 + LN_EPS);
        #pragma unroll
        for (int nt = 0; nt < NT8; nt++) {
            int n0 = nt * 8 + cbase;
            bool valid = n0 < NOUT;
            float v0 = 0.f, v1 = 0.f, v2 = 0.f, v3 = 0.f;
            if (valid) {
                float2 gg = *(const float2*)(gamma + n0);
                float2 bb = *(const float2*)(beta + n0);
                v0 = fmaxf(0.f, (acc[nt][0] - mu0) * rs0 * gg.x + bb.x);
                v1 = fmaxf(0.f, (acc[nt][1] - mu0) * rs0 * gg.y + bb.y);
                v2 = fmaxf(0.f, (acc[nt][2] - mu1) * rs1 * gg.x + bb.x);
                v3 = fmaxf(0.f, (acc[nt][3] - mu1) * rs1 * gg.y + bb.y);
            }
            if (r0 < M)
                *(uint32_t*)(OH + (size_t)r0 * 128 + n0) = packh2(v0, v1);
            if (r1 < M)
                *(uint32_t*)(OH + (size_t)r1 * 128 + n0) = packh2(v2, v3);
        }
    } else if constexpr (EPI == 2) {
        float d0 = (r0 < M) ? dinv[r0] : 0.f;
        float d1 = (r1 < M) ? dinv[r1] : 0.f;
        #pragma unroll
        for (int nt = 0; nt < NT8; nt++) {
            int n0 = nt * 8 + cbase;
            bool valid = n0 < NOUT;
            float v0 = valid ? acc[nt][0] * d0 : 0.f;
            float v1 = valid ? acc[nt][1] * d0 : 0.f;
            float v2 = valid ? acc[nt][2] * d1 : 0.f;
            float v3 = valid ? acc[nt][3] * d1 : 0.f;
            if (r0 < M)
                *(uint32_t*)(OH + (size_t)r0 * 128 + n0) = packh2(v0, v1);
            if (r1 < M)
                *(uint32_t*)(OH + (size_t)r1 * 128 + n0) = packh2(v2, v3);
        }
    } else {  // EPI == 3
        constexpr int NTH = NT8 / 2;
        #pragma unroll
        for (int nt = 0; nt < NTH; nt++) {
            int n0 = nt * 8 + cbase;
            bool valid = n0 < NOUT;
            float v0 = valid ? acc[nt][0] : 0.f;
            float v1 = valid ? acc[nt][1] : 0.f;
            float v2 = valid ? acc[nt][2] : 0.f;
            float v3 = valid ? acc[nt][3] : 0.f;
            if (r0 < M)
                *(uint32_t*)(OH + (size_t)r0 * 128 + n0) = packh2(v0, v1);
            if (r1 < M)
                *(uint32_t*)(OH + (size_t)r1 * 128 + n0) = packh2(v2, v3);
        }
        #pragma unroll
        for (int nt = NTH; nt < NT8; nt++) {
            int n0 = (nt - NTH) * 8 + cbase;
            if (n0 < NOUT) {
                float2 bb = *(const float2*)(bias + n0);
                if (r0 < M)
                    *(float2*)(out2 + (size_t)r0 * NOUT + n0) =
                        make_float2(acc[nt][0] + bb.x, acc[nt][1] + bb.y);
                if (r1 < M)
                    *(float2*)(out2 + (size_t)r1 * NOUT + n0) =
                        make_float2(acc[nt][2] + bb.x, acc[nt][3] + bb.y);
            }
        }
    }
}

// ---------------- CSR construction ----------------
__global__ void zero_cnt_kernel() {
    int i = blockIdx.x * blockDim.x + threadIdx.x;
    if (i < NN) g_cnt[i] = 0;
}
__global__ void count_kernel(const int* __restrict__ tgt) {
    int e = blockIdx.x * blockDim.x + threadIdx.x;
    if (e < EE) atomicAdd(&g_cnt[tgt[e]], 1);
}
// phase A: per-block exclusive scan + block sums
__global__ void scanA_kernel() {
    __shared__ int ws[32];
    int tid = threadIdx.x, lane = tid & 31, w = tid >> 5;
    int i = blockIdx.x * 1024 + tid;
    int v = (i < NN) ? g_cnt[i] : 0;
    int x = v;
    #pragma unroll
    for (int o = 1; o < 32; o <<= 1) {
        int t = __shfl_up_sync(0xffffffffu, x, o);
        if (lane >= o) x += t;
    }
    if (lane == 31) ws[w] = x;
    __syncthreads();
    if (w == 0) {
        int y = ws[lane];
        #pragma unroll
        for (int o = 1; o < 32; o <<= 1) {
            int t = __shfl_up_sync(0xffffffffu, y, o);
            if (lane >= o) y += t;
        }
        ws[lane] = y;
    }
    __syncthreads();
    int ex = ((w > 0) ? ws[w - 1] : 0) + x - v;
    if (i < NN) g_rowptr[i] = ex;
    if (tid == 1023) g_bsum[blockIdx.x] = ws[31];
}
// phase B: scan NBLK block sums (1 block, 64 threads)
__global__ void scanB_kernel() {
    __shared__ int wsum[2];
    int tid = threadIdx.x, lane = tid & 31, w = tid >> 5;
    int v = (tid < NBLK) ? g_bsum[tid] : 0;
    int x = v;
    #pragma unroll
    for (int o = 1; o < 32; o <<= 1) {
        int t = __shfl_up_sync(0xffffffffu, x, o);
        if (lane >= o) x += t;
    }
    if (lane == 31) wsum[w] = x;
    __syncthreads();
    int ex = ((w == 1) ? wsum[0] : 0) + x - v;
    g_boff[tid] = ex;
}
// phase C: add offsets, init cur, compute dinv, set rowptr[NN]
__global__ void scanC_kernel() {
    int i = blockIdx.x * 1024 + threadIdx.x;
    if (i < NN) {
        int rp = g_rowptr[i] + g_boff[blockIdx.x];
        g_rowptr[i] = rp;
        g_cur[i]    = rp;
        g_dinv[i]   = rsqrtf((float)(g_cnt[i] + 1));
    }
    if (i == 0) g_rowptr[NN] = g_boff[NBLK];
}
__global__ void fill_kernel(const int* __restrict__ src, const int* __restrict__ tgt) {
    int e = blockIdx.x * blockDim.x + threadIdx.x;
    if (e < EE) {
        int pos = atomicAdd(&g_cur[tgt[e]], 1);
        g_csr[pos] = src[e];
    }
}

// ---------------- gather over fp16 message planes ----------------
// MODE 0: init = fp32 self buf, relu -> fp16 plane
// MODE 1: init = msg[v], *dinv + bias, relu -> fp16 plane
// MODE 2: init = msg[v], *dinv + bias, log_softmax(C=64) -> fp32 out
template <int MODE>
__global__ void gather_kernel(const __half* __restrict__ msg,
                              const float* __restrict__ initF,
                              const float* __restrict__ bias,
                              float* __restrict__ out,
                              __half* __restrict__ OUT)
{
    int warp = (blockIdx.x * blockDim.x + threadIdx.x) >> 5;
    int lane = threadIdx.x & 31;
    if (warp >= NN) return;
    constexpr int NL = (MODE == 2) ? 8 : 13;
    bool act = lane < NL;

    float acc[8];
    #pragma unroll
    for (int i = 0; i < 8; i++) acc[i] = 0.f;

    if (MODE == 0) {
        if (act) {
            const float* ip = initF + (size_t)warp * HID + lane * 8;
            float4 f = __ldg((const float4*)ip);
            acc[0] = f.x; acc[1] = f.y; acc[2] = f.z; acc[3] = f.w;
            if (lane * 8 + 8 <= HID) {
                float4 g = __ldg((const float4*)(ip + 4));
                acc[4] = g.x; acc[5] = g.y; acc[6] = g.z; acc[7] = g.w;
            }
        }
    } else {
        if (act)
            acc8(acc, __ldg((const uint4*)(msg + (size_t)warp * 128) + lane));
    }

    int e = g_rowptr[warp], end = g_rowptr[warp + 1];
    for (; e + 1 < end; e += 2) {
        int s0 = g_csr[e], s1 = g_csr[e + 1];
        if (act) {
            uint4 v0 = __ldg((const uint4*)(msg + (size_t)s0 * 128) + lane);
            uint4 v1 = __ldg((const uint4*)(msg + (size_t)s1 * 128) + lane);
            acc8(acc, v0); acc8(acc, v1);
        }
    }
    if (e < end) {
        int s0 = g_csr[e];
        if (act)
            acc8(acc, __ldg((const uint4*)(msg + (size_t)s0 * 128) + lane));
    }

    if (MODE == 0) {
        if (act) {
            uint4 o; __half2* h = (__half2*)&o;
            #pragma unroll
            for (int i = 0; i < 4; i++)
                h[i] = __floats2half2_rn(fmaxf(0.f, acc[2 * i]),
                                         fmaxf(0.f, acc[2 * i + 1]));
            *((uint4*)(OUT + (size_t)warp * 128) + lane) = o;
        }
    } else {
        float d = g_dinv[warp];
        float t[8];
        #pragma unroll
        for (int i = 0; i < 8; i++) t[i] = 0.f;
        if (act) {
            const float* bp = bias + lane * 8;
            float4 b0 = __ldg((const float4*)bp);
            t[0] = acc[0] * d + b0.x; t[1] = acc[1] * d + b0.y;
            t[2] = acc[2] * d + b0.z; t[3] = acc[3] * d + b0.w;
            if (MODE == 2 || lane * 8 + 8 <= HID) {
                float4 b1 = __ldg((const float4*)(bp + 4));
                t[4] = acc[4] * d + b1.x; t[5] = acc[5] * d + b1.y;
                t[6] = acc[6] * d + b1.z; t[7] = acc[7] * d + b1.w;
            }
        }
        if (MODE == 1) {
            if (act) {
                uint4 o; __half2* h = (__half2*)&o;
                #pragma unroll
                for (int i = 0; i < 4; i++)
                    h[i] = __floats2half2_rn(fmaxf(0.f, t[2 * i]),
                                             fmaxf(0.f, t[2 * i + 1]));
                *((uint4*)(OUT + (size_t)warp * 128) + lane) = o;
            }
        } else {
            float m = -1e30f;
            if (act) {
                #pragma unroll
                for (int i = 0; i < 8; i++) m = fmaxf(m, t[i]);
            }
            #pragma unroll
            for (int o = 16; o; o >>= 1)
                m = fmaxf(m, __shfl_xor_sync(0xffffffffu, m, o));
            float se = 0.f;
            if (act) {
                #pragma unroll
                for (int i = 0; i < 8; i++) se += expf(t[i] - m);
            }
            #pragma unroll
            for (int o = 16; o; o >>= 1)
                se += __shfl_xor_sync(0xffffffffu, se, o);
            float lse = logf(se);
            if (act) {
                float* op = out + (size_t)warp * DOUT + lane * 8;
                *(float4*)op = make_float4(t[0] - m - lse, t[1] - m - lse,
                                           t[2] - m - lse, t[3] - m - lse);
                *(float4*)(op + 4) = make_float4(t[4] - m - lse, t[5] - m - lse,
                                                 t[6] - m - lse, t[7] - m - lse);
            }
        }
    }
}

// ---------------- launcher ----------------
extern "C" void kernel_launch(void* const* d_in, const int* in_sizes, int n_in,
                              void* d_out, int out_size)
{
    const float* X     = (const float*)d_in[0];
    const int*   EI    = (const int*)d_in[1];
    const float* W1    = (const float*)d_in[3];
    const float* b1    = (const float*)d_in[4];
    const float* g1    = (const float*)d_in[5];
    const float* be1   = (const float*)d_in[6];
    const float* W2    = (const float*)d_in[7];
    const float* b2    = (const float*)d_in[8];
    const float* g2    = (const float*)d_in[9];
    const float* be2   = (const float*)d_in[10];
    const float* Wrel  = (const float*)d_in[11];
    const float* Wself = (const float*)d_in[12];
    const float* rb    = (const float*)d_in[13];
    const float* c1W   = (const float*)d_in[14];
    const float* c1b   = (const float*)d_in[15];
    const float* c2W   = (const float*)d_in[16];
    const float* c2b   = (const float*)d_in[17];

    const int* src = EI;
    const int* tgt = EI + EE;

    __half *h1, *h2, *h3;
    float *selfp, *dinvp;
    uint4* wf;
    cudaGetSymbolAddress((void**)&h1, g_hp1);
    cudaGetSymbolAddress((void**)&h2, g_hp2);
    cudaGetSymbolAddress((void**)&h3, g_hp3);
    cudaGetSymbolAddress((void**)&selfp, g_self);
    cudaGetSymbolAddress((void**)&dinvp, g_dinv);
    cudaGetSymbolAddress((void**)&wf, g_wfrag);

    // --- weight pre-pack + CSR (cheap) ---
    wfrag_all<<<(26752 + 255) / 256, 256>>>(W1, W2, Wrel, Wself, c1W, c2W, wf);
    zero_cnt_kernel<<<(NN + 255) / 256, 256>>>();
    count_kernel<<<(EE + 255) / 256, 256>>>(tgt);
    scanA_kernel<<<NBLK, 1024>>>();
    scanB_kernel<<<1, 64>>>();
    scanC_kernel<<<NBLK, 1024>>>();
    fill_kernel<<<(EE + 255) / 256, 256>>>(src, tgt);

    const int MB = (NN + 127) / 128;   // 391
    const int WB = (NN + 7) / 8;       // 6250
    const int SMEM = 16384 + 1024;

    // --- MLP ---
    gemm_mma<0, DIN, 32, 13, HID, 1><<<MB, 256, SMEM>>>(
        X, nullptr, wf + OFF_W1, b1, g1, be1, nullptr, nullptr, h1, NN);
    gemm_mma<1, 104, 7, 13, HID, 1><<<MB, 256, SMEM>>>(
        nullptr, h1, wf + OFF_W2, b2, g2, be2, nullptr, nullptr, h2, NN);

    // --- RGCN: msg fp16 -> h3, self fp32 -> g_self ---
    gemm_mma<1, 104, 7, 26, HID, 3><<<MB, 256, SMEM>>>(
        nullptr, h2, wf + OFF_FUSED, rb, nullptr, nullptr, nullptr, selfp, h3, NN);
    gather_kernel<0><<<WB, 256>>>(h3, selfp, nullptr, nullptr, h1);

    // --- GCNConv 1 ---
    gemm_mma<1, 104, 7, 13, HID, 2><<<MB, 256, SMEM>>>(
        nullptr, h1, wf + OFF_C1, nullptr, nullptr, nullptr, dinvp, nullptr, h2, NN);
    gather_kernel<1><<<WB, 256>>>(h2, nullptr, c1b, nullptr, h3);

    // --- GCNConv 2 (100->64) + log_softmax ---
    gemm_mma<1, 104, 7, 8, DOUT, 2><<<MB, 256, SMEM>>>(
        nullptr, h3, wf + OFF_C2, nullptr, nullptr, nullptr, dinvp, nullptr, h1, NN);
    gather_kernel<2><<<WB, 256>>>(h1, nullptr, c2b, (float*)d_out, nullptr);
}